// round 5
// baseline (speedup 1.0000x reference)
#include <cuda_runtime.h>
#include <stdint.h>

#define HW    96
#define NPIX  9216          // 96*96
#define NIMG  32
#define NTRAIN 100
#define NPC   50
#define KNN   5

struct Keys { unsigned int k[NIMG][4]; };   // per image: kfg0,kfg1,kbg0,kbg1

// ---------------------------------------------------------------------------
// threefry2x32 (JAX-exact): rotations {13,15,26,6},{17,29,16,24}, 5 blocks
// ---------------------------------------------------------------------------
__host__ __device__ __forceinline__ void threefry2x32(
    unsigned int k0, unsigned int k1,
    unsigned int x0, unsigned int x1,
    unsigned int &o0, unsigned int &o1)
{
    unsigned int ks[3];
    ks[0] = k0; ks[1] = k1; ks[2] = k0 ^ k1 ^ 0x1BD11BDAu;
    x0 += ks[0]; x1 += ks[1];
    const int rot[8] = {13, 15, 26, 6, 17, 29, 16, 24};
#pragma unroll
    for (int i = 0; i < 5; ++i) {
#pragma unroll
        for (int j = 0; j < 4; ++j) {
            int r = rot[(i & 1) * 4 + j];
            x0 += x1;
            x1 = (x1 << r) | (x1 >> (32 - r));
            x1 ^= x0;
        }
        x0 += ks[(i + 1) % 3];
        x1 += ks[(i + 2) % 3] + (unsigned int)(i + 1);
    }
    o0 = x0; o1 = x1;
}

// partitionable-mode 32-bit random word for flat index i (iota64: hi=0, lo=i)
__device__ __forceinline__ unsigned int tf_bits32(unsigned int k0, unsigned int k1,
                                                  unsigned int i)
{
    unsigned int r0, r1;
    threefry2x32(k0, k1, 0u, i, r0, r1);
    return r0 ^ r1;
}

__device__ __forceinline__ float bits_to_unit_float(unsigned int bits)
{
    // JAX uniform: (bits>>9 | 0x3f800000) as float - 1.0
    unsigned int fb = (bits >> 9) | 0x3f800000u;
    return __uint_as_float(fb) - 1.0f;
}

__device__ __forceinline__ float clip01(float x)
{
    return fminf(fmaxf(x, 0.0f), 1.0f);
}

// ---------------------------------------------------------------------------
// scratch (no cudaMalloc allowed)
// ---------------------------------------------------------------------------
__device__ float g_train[NIMG][NTRAIN][5];   // standardized train features
__device__ float g_mean[NIMG][5];
__device__ float g_std[NIMG][5];

// ---------------------------------------------------------------------------
// Kernel 1: per-image sampling + train-set build.  1 block / image.
// ---------------------------------------------------------------------------
__global__ __launch_bounds__(1024) void k1_sample(const float* __restrict__ img, Keys kp)
{
    const int b = blockIdx.x;
    const int t = threadIdx.x;
    const int lane = t & 31;
    const int warp = t >> 5;
    const float* im = img + (size_t)b * NPIX * 3;

    __shared__ float score[NPIX];        // 36 KB
    __shared__ float redv[32];
    __shared__ int   redi[32];
    __shared__ int   chmaxi[3];
    __shared__ int   sel[2 * NPC];
    __shared__ float trf[NTRAIN][5];
    __shared__ float smean[5], sstd[5];

    // ---- per-channel max of clipped image ----
    if (t < 3) chmaxi[t] = 0;
    __syncthreads();
    float m0 = 0.f, m1 = 0.f, m2 = 0.f;
    for (int p = t; p < NPIX; p += 1024) {
        m0 = fmaxf(m0, clip01(im[p * 3 + 0] / 255.0f));
        m1 = fmaxf(m1, clip01(im[p * 3 + 1] / 255.0f));
        m2 = fmaxf(m2, clip01(im[p * 3 + 2] / 255.0f));
    }
    atomicMax(&chmaxi[0], __float_as_int(m0));
    atomicMax(&chmaxi[1], __float_as_int(m1));
    atomicMax(&chmaxi[2], __float_as_int(m2));
    __syncthreads();
    const float cm0 = __int_as_float(chmaxi[0]);
    const float cm1 = __int_as_float(chmaxi[1]);
    const float cm2 = __int_as_float(chmaxi[2]);

    // ---- two passes: fg (pass 0), bg (pass 1) ----
    for (int pass = 0; pass < 2; ++pass) {
        const unsigned int kk0 = kp.k[b][pass * 2 + 0];
        const unsigned int kk1 = kp.k[b][pass * 2 + 1];

        // partitionable random_bits: word p = xor of threefry(key, 0, p)
        for (int p = t; p < NPIX; p += 1024) {
            unsigned int bits = tf_bits32(kk0, kk1, (unsigned int)p);
            float v0 = clip01(im[p * 3 + 0] / 255.0f);
            float v1 = clip01(im[p * 3 + 1] / 255.0f);
            float v2 = clip01(im[p * 3 + 2] / 255.0f);
            float n0 = v0 / cm0, n1 = v1 / cm1, n2 = v2 / cm2;
            bool fg = (n0 > 0.f && n0 < 0.6f) ||
                      (n1 > 0.f && n1 < 0.6f) ||
                      (n2 > 0.f && n2 < 0.6f);
            bool valid = pass ? (!fg) : fg;
            score[p] = valid ? bits_to_unit_float(bits) : -1.0f;
        }
        __syncthreads();

        // ---- 50 argmax passes; tie-break lowest index (JAX top_k stable) ----
        for (int s = 0; s < NPC; ++s) {
            float bv = -3.0f; int bi = NPIX;
            for (int p = t; p < NPIX; p += 1024) {
                float v = score[p];
                if (v > bv) { bv = v; bi = p; }   // ascending p -> lowest p on tie
            }
            // warp reduce (argmax, tie lowest index)
#pragma unroll
            for (int off = 16; off > 0; off >>= 1) {
                float ov = __shfl_down_sync(0xffffffffu, bv, off);
                int   oi = __shfl_down_sync(0xffffffffu, bi, off);
                if (ov > bv || (ov == bv && oi < bi)) { bv = ov; bi = oi; }
            }
            if (lane == 0) { redv[warp] = bv; redi[warp] = bi; }
            __syncthreads();
            if (warp == 0) {
                bv = redv[lane]; bi = redi[lane];
#pragma unroll
                for (int off = 16; off > 0; off >>= 1) {
                    float ov = __shfl_down_sync(0xffffffffu, bv, off);
                    int   oi = __shfl_down_sync(0xffffffffu, bi, off);
                    if (ov > bv || (ov == bv && oi < bi)) { bv = ov; bi = oi; }
                }
                if (lane == 0) { sel[pass * NPC + s] = bi; score[bi] = -2.0f; }
            }
            __syncthreads();
        }
    }

    // ---- train features (fg first then bg, top_k order) ----
    if (t < NTRAIN) {
        int idx = sel[t];
        int ii = idx / HW, jj = idx % HW;
        trf[t][0] = clip01(im[idx * 3 + 0] / 255.0f) / 255.0f;
        trf[t][1] = clip01(im[idx * 3 + 1] / 255.0f) / 255.0f;
        trf[t][2] = clip01(im[idx * 3 + 2] / 255.0f) / 255.0f;
        trf[t][3] = (float)ii / 96.0f * 100.0f;
        trf[t][4] = (float)jj / 96.0f * 100.0f;
    }
    __syncthreads();

    if (t < 5) {
        float s = 0.f;
        for (int j = 0; j < NTRAIN; ++j) s += trf[j][t];
        float mean = s / (float)NTRAIN;
        float s2 = 0.f;
        for (int j = 0; j < NTRAIN; ++j) {
            float d = trf[j][t] - mean;
            s2 += d * d;
        }
        float sd = sqrtf(s2 / (float)NTRAIN);
        smean[t] = mean; sstd[t] = sd;
        g_mean[b][t] = mean; g_std[b][t] = sd;
    }
    __syncthreads();

    if (t < NTRAIN * 5) {
        int j = t / 5, d = t % 5;
        g_train[b][j][d] = (trf[j][d] - smean[d]) / sstd[d];
    }
}

// ---------------------------------------------------------------------------
// Kernel 2: KNN classify + mask.  blockIdx.y = image, 256 thr = 256 pixels.
// ---------------------------------------------------------------------------
__global__ __launch_bounds__(256) void k2_knn(const float* __restrict__ img,
                                              float* __restrict__ out)
{
    const int b = blockIdx.y;
    const int t = threadIdx.x;
    const int p = blockIdx.x * 256 + t;

    __shared__ float trs[NTRAIN * 5];
    __shared__ float sm[5], ss[5];

    const float* gt = &g_train[b][0][0];
    for (int i = t; i < NTRAIN * 5; i += 256) trs[i] = gt[i];
    if (t < 5)            sm[t] = g_mean[b][t];
    else if (t < 10)      ss[t - 5] = g_std[b][t - 5];
    __syncthreads();

    const float* im = img + (size_t)b * NPIX * 3;

    float v0 = clip01(im[p * 3 + 0] / 255.0f);
    float v1 = clip01(im[p * 3 + 1] / 255.0f);
    float v2 = clip01(im[p * 3 + 2] / 255.0f);

    float f[5];
    f[0] = v0 / 255.0f;
    f[1] = v1 / 255.0f;
    f[2] = v2 / 255.0f;
    f[3] = (float)(p / HW) / 96.0f * 100.0f;
    f[4] = (float)(p % HW) / 96.0f * 100.0f;
#pragma unroll
    for (int d = 0; d < 5; ++d) f[d] = (f[d] - sm[d]) / ss[d];

    // top-5 smallest squared distances (register sorted list, stable on ties)
    float d0 = 1e30f, d1 = 1e30f, d2 = 1e30f, d3 = 1e30f, d4 = 1e30f;
    int   i0 = -1, i1 = -1, i2 = -1, i3 = -1, i4 = -1;

    for (int j = 0; j < NTRAIN; ++j) {
        float dsq = 0.f;
#pragma unroll
        for (int d = 0; d < 5; ++d) {
            float df = f[d] - trs[j * 5 + d];
            dsq += df * df;
        }
        if (dsq < d4) {
            d4 = dsq; i4 = j;
            if (d4 < d3) { float tv = d3; d3 = d4; d4 = tv; int ti = i3; i3 = i4; i4 = ti; }
            if (d3 < d2) { float tv = d2; d2 = d3; d3 = tv; int ti = i2; i2 = i3; i3 = ti; }
            if (d2 < d1) { float tv = d1; d1 = d2; d2 = tv; int ti = i1; i1 = i2; i2 = ti; }
            if (d1 < d0) { float tv = d0; d0 = d1; d1 = tv; int ti = i0; i0 = i1; i1 = ti; }
        }
    }

    int cnt = (i0 < NPC) + (i1 < NPC) + (i2 < NPC) + (i3 < NPC) + (i4 < NPC);
    bool seg = (cnt >= 2);   // probas = cnt/5 >= 0.3

    float* o = out + (size_t)b * NPIX * 3 + (size_t)p * 3;
    o[0] = seg ? v0 : 0.0f;
    o[1] = seg ? v1 : 0.0f;
    o[2] = seg ? v2 : 0.0f;
}

// ---------------------------------------------------------------------------
// host: derive JAX keys — PARTITIONABLE threefry (default since JAX 0.4.36):
//   split(key, n):  key_i = threefry(key, hi(i)=0, lo(i)=i) -> (r0, r1)
// ---------------------------------------------------------------------------
static void compute_keys(Keys& kp)
{
    for (int b = 0; b < NIMG; ++b) {
        unsigned int ik0, ik1;
        threefry2x32(0u, 42u, 0u, (unsigned int)b, ik0, ik1);   // split(key(42),32)[b]
        unsigned int f0, f1, g0, g1;
        threefry2x32(ik0, ik1, 0u, 0u, f0, f1);                 // split(imgkey)[0] = k_fg
        threefry2x32(ik0, ik1, 0u, 1u, g0, g1);                 // split(imgkey)[1] = k_bg
        kp.k[b][0] = f0; kp.k[b][1] = f1;
        kp.k[b][2] = g0; kp.k[b][3] = g1;
    }
}

extern "C" void kernel_launch(void* const* d_in, const int* in_sizes, int n_in,
                              void* d_out, int out_size)
{
    const float* img = (const float*)d_in[0];
    float* out = (float*)d_out;
    (void)in_sizes; (void)n_in; (void)out_size;

    Keys kp;
    compute_keys(kp);

    k1_sample<<<NIMG, 1024>>>(img, kp);
    dim3 g2(NPIX / 256, NIMG);
    k2_knn<<<g2, 256>>>(img, out);
}

// round 6
// speedup vs baseline: 1.7422x; 1.7422x over previous
#include <cuda_runtime.h>
#include <stdint.h>

#define HW    96
#define NPIX  9216          // 96*96
#define NIMG  32
#define NTRAIN 100
#define NPC   50
#define KNN   5
#define CAP   1024          // candidate buffer capacity

struct Keys { unsigned int k[NIMG][4]; };   // per image: kfg0,kfg1,kbg0,kbg1

// ---------------------------------------------------------------------------
// threefry2x32 (JAX-exact)
// ---------------------------------------------------------------------------
__host__ __device__ __forceinline__ void threefry2x32(
    unsigned int k0, unsigned int k1,
    unsigned int x0, unsigned int x1,
    unsigned int &o0, unsigned int &o1)
{
    unsigned int ks[3];
    ks[0] = k0; ks[1] = k1; ks[2] = k0 ^ k1 ^ 0x1BD11BDAu;
    x0 += ks[0]; x1 += ks[1];
    const int rot[8] = {13, 15, 26, 6, 17, 29, 16, 24};
#pragma unroll
    for (int i = 0; i < 5; ++i) {
#pragma unroll
        for (int j = 0; j < 4; ++j) {
            int r = rot[(i & 1) * 4 + j];
            x0 += x1;
            x1 = (x1 << r) | (x1 >> (32 - r));
            x1 ^= x0;
        }
        x0 += ks[(i + 1) % 3];
        x1 += ks[(i + 2) % 3] + (unsigned int)(i + 1);
    }
    o0 = x0; o1 = x1;
}

// partitionable-mode 32-bit random word for flat index i (iota64: hi=0, lo=i)
__device__ __forceinline__ unsigned int tf_bits32(unsigned int k0, unsigned int k1,
                                                  unsigned int i)
{
    unsigned int r0, r1;
    threefry2x32(k0, k1, 0u, i, r0, r1);
    return r0 ^ r1;
}

__device__ __forceinline__ float bits_to_unit_float(unsigned int bits)
{
    unsigned int fb = (bits >> 9) | 0x3f800000u;
    return __uint_as_float(fb) - 1.0f;
}

__device__ __forceinline__ float clip01(float x)
{
    return fminf(fmaxf(x, 0.0f), 1.0f);
}

// ---------------------------------------------------------------------------
// scratch — train features stored SoA: [b][d*100 + j], 125 float4 per image
// ---------------------------------------------------------------------------
__device__ float4 g_train4[NIMG][125];
__device__ float  g_mean[NIMG][5];
__device__ float  g_std[NIMG][5];

// ---------------------------------------------------------------------------
// Kernel 1: per-image sampling + train-set build.  1 block / image.
// ---------------------------------------------------------------------------
__global__ __launch_bounds__(1024) void k1_sample(const float* __restrict__ img, Keys kp)
{
    const int b = blockIdx.x;
    const int t = threadIdx.x;
    const int lane = t & 31;
    const int warp = t >> 5;
    const float* im = img + (size_t)b * NPIX * 3;

    __shared__ float score[NPIX];        // 36 KB
    __shared__ int   hist[256];
    __shared__ int   cidx[CAP];
    __shared__ int   s_B, s_cnt;
    __shared__ float redv[32];
    __shared__ int   redi[32];
    __shared__ int   chmaxi[3];
    __shared__ int   sel[2 * NPC];
    __shared__ float trf[NTRAIN][5];
    __shared__ float smean[5], sstd[5];

    // ---- per-channel max of clipped image ----
    if (t < 3) chmaxi[t] = 0;
    __syncthreads();
    float m0 = 0.f, m1 = 0.f, m2 = 0.f;
    for (int p = t; p < NPIX; p += 1024) {
        m0 = fmaxf(m0, clip01(im[p * 3 + 0] / 255.0f));
        m1 = fmaxf(m1, clip01(im[p * 3 + 1] / 255.0f));
        m2 = fmaxf(m2, clip01(im[p * 3 + 2] / 255.0f));
    }
    atomicMax(&chmaxi[0], __float_as_int(m0));
    atomicMax(&chmaxi[1], __float_as_int(m1));
    atomicMax(&chmaxi[2], __float_as_int(m2));
    __syncthreads();
    const float cm0 = __int_as_float(chmaxi[0]);
    const float cm1 = __int_as_float(chmaxi[1]);
    const float cm2 = __int_as_float(chmaxi[2]);

    // ---- two passes: fg (pass 0), bg (pass 1) ----
    for (int pass = 0; pass < 2; ++pass) {
        const unsigned int kk0 = kp.k[b][pass * 2 + 0];
        const unsigned int kk1 = kp.k[b][pass * 2 + 1];

        if (t < 256) hist[t] = 0;
        __syncthreads();

        // scores + histogram (scores uniform in [0,1) for valid, -1 invalid)
        for (int p = t; p < NPIX; p += 1024) {
            unsigned int bits = tf_bits32(kk0, kk1, (unsigned int)p);
            float v0 = clip01(im[p * 3 + 0] / 255.0f);
            float v1 = clip01(im[p * 3 + 1] / 255.0f);
            float v2 = clip01(im[p * 3 + 2] / 255.0f);
            float n0 = v0 / cm0, n1 = v1 / cm1, n2 = v2 / cm2;
            bool fg = (n0 > 0.f && n0 < 0.6f) ||
                      (n1 > 0.f && n1 < 0.6f) ||
                      (n2 > 0.f && n2 < 0.6f);
            bool valid = pass ? (!fg) : fg;
            float sc = valid ? bits_to_unit_float(bits) : -1.0f;
            score[p] = sc;
            if (valid) {
                int bin = min((int)(sc * 256.0f), 255);
                atomicAdd(&hist[bin], 1);
            }
        }
        __syncthreads();

        // threshold bin: smallest B with count(bin >= B) >= NPC
        if (t == 0) {
            int total = 0, B = -1;
            for (int bin = 255; bin >= 0; --bin) {
                total += hist[bin];
                if (total >= NPC) { B = bin; break; }
            }
            s_B = B; s_cnt = 0;
        }
        __syncthreads();
        const int B = s_B;

        bool fast_ok = false;
        if (B >= 0) {
            // collect candidates with bin >= B
            for (int p = t; p < NPIX; p += 1024) {
                float v = score[p];
                if (v >= 0.0f) {
                    int bin = min((int)(v * 256.0f), 255);
                    if (bin >= B) {
                        int pos = atomicAdd(&s_cnt, 1);
                        if (pos < CAP) cidx[pos] = p;
                    }
                }
            }
            __syncthreads();
            const int cnt = s_cnt;
            if (cnt <= CAP) {
                fast_ok = true;
                if (t < cnt) {
                    int myi = cidx[t];
                    float myv = score[myi];
                    int rank = 0;
                    for (int j = 0; j < cnt; ++j) {
                        int oj = cidx[j];
                        float ov = score[oj];
                        rank += (ov > myv) || (ov == myv && oj < myi);
                    }
                    if (rank < NPC) sel[pass * NPC + rank] = myi;
                }
            }
            __syncthreads();
        }

        if (!fast_ok) {
            // fallback: 50 serialized argmax passes (deterministic safety net)
            for (int s = 0; s < NPC; ++s) {
                float bv = -3.0f; int bi = NPIX;
                for (int p = t; p < NPIX; p += 1024) {
                    float v = score[p];
                    if (v > bv) { bv = v; bi = p; }
                }
#pragma unroll
                for (int off = 16; off > 0; off >>= 1) {
                    float ov = __shfl_down_sync(0xffffffffu, bv, off);
                    int   oi = __shfl_down_sync(0xffffffffu, bi, off);
                    if (ov > bv || (ov == bv && oi < bi)) { bv = ov; bi = oi; }
                }
                if (lane == 0) { redv[warp] = bv; redi[warp] = bi; }
                __syncthreads();
                if (warp == 0) {
                    bv = redv[lane]; bi = redi[lane];
#pragma unroll
                    for (int off = 16; off > 0; off >>= 1) {
                        float ov = __shfl_down_sync(0xffffffffu, bv, off);
                        int   oi = __shfl_down_sync(0xffffffffu, bi, off);
                        if (ov > bv || (ov == bv && oi < bi)) { bv = ov; bi = oi; }
                    }
                    if (lane == 0) { sel[pass * NPC + s] = bi; score[bi] = -2.0f; }
                }
                __syncthreads();
            }
        }
    }

    // ---- train features (fg first then bg, top_k order) ----
    if (t < NTRAIN) {
        int idx = sel[t];
        int ii = idx / HW, jj = idx % HW;
        trf[t][0] = clip01(im[idx * 3 + 0] / 255.0f) / 255.0f;
        trf[t][1] = clip01(im[idx * 3 + 1] / 255.0f) / 255.0f;
        trf[t][2] = clip01(im[idx * 3 + 2] / 255.0f) / 255.0f;
        trf[t][3] = (float)ii / 96.0f * 100.0f;
        trf[t][4] = (float)jj / 96.0f * 100.0f;
    }
    __syncthreads();

    if (t < 5) {
        float s = 0.f;
        for (int j = 0; j < NTRAIN; ++j) s += trf[j][t];
        float mean = s / (float)NTRAIN;
        float s2 = 0.f;
        for (int j = 0; j < NTRAIN; ++j) {
            float d = trf[j][t] - mean;
            s2 += d * d;
        }
        float sd = sqrtf(s2 / (float)NTRAIN);
        smean[t] = mean; sstd[t] = sd;
        g_mean[b][t] = mean; g_std[b][t] = sd;
    }
    __syncthreads();

    // standardized train, SoA: [d*100 + j]
    if (t < NTRAIN * 5) {
        int j = t / 5, d = t % 5;
        float* gt = (float*)&g_train4[b][0];
        gt[d * NTRAIN + j] = (trf[j][d] - smean[d]) / sstd[d];
    }
}

// ---------------------------------------------------------------------------
// Kernel 2: KNN classify + mask.  blockIdx.y = image, 256 thr = 512 pixels.
// ---------------------------------------------------------------------------
#define PXB 512
__global__ __launch_bounds__(256) void k2_knn(const float* __restrict__ img,
                                              float* __restrict__ out)
{
    const int b = blockIdx.y;
    const int t = threadIdx.x;
    const int base = blockIdx.x * PXB;

    __shared__ float4 trs4[125];   // SoA: trs4[d*25 + q] = train_s[d][4q..4q+3]
    __shared__ float sm[5], ss[5];

    if (t < 125) trs4[t] = g_train4[b][t];
    if (t >= 128 && t < 133)      sm[t - 128] = g_mean[b][t - 128];
    else if (t >= 160 && t < 165) ss[t - 160] = g_std[b][t - 160];
    __syncthreads();

    const float* im = img + (size_t)b * NPIX * 3;

    float v[2][3];
    float f[2][5];
    float dd[2][5];
    int   id[2][5];
#pragma unroll
    for (int px = 0; px < 2; ++px) {
        int p = base + px * 256 + t;
        v[px][0] = clip01(im[p * 3 + 0] / 255.0f);
        v[px][1] = clip01(im[p * 3 + 1] / 255.0f);
        v[px][2] = clip01(im[p * 3 + 2] / 255.0f);
        f[px][0] = (v[px][0] / 255.0f - sm[0]) / ss[0];
        f[px][1] = (v[px][1] / 255.0f - sm[1]) / ss[1];
        f[px][2] = (v[px][2] / 255.0f - sm[2]) / ss[2];
        f[px][3] = ((float)(p / HW) / 96.0f * 100.0f - sm[3]) / ss[3];
        f[px][4] = ((float)(p % HW) / 96.0f * 100.0f - sm[4]) / ss[4];
#pragma unroll
        for (int s = 0; s < 5; ++s) { dd[px][s] = 1e30f; id[px][s] = NTRAIN; }
    }

    for (int jb = 0; jb < NTRAIN / 4; ++jb) {
        float ta[5][4];
#pragma unroll
        for (int d = 0; d < 5; ++d)
            *(float4*)ta[d] = trs4[d * 25 + jb];
#pragma unroll
        for (int u = 0; u < 4; ++u) {
            int j = jb * 4 + u;
#pragma unroll
            for (int px = 0; px < 2; ++px) {
                float dsq = 0.f;
#pragma unroll
                for (int d = 0; d < 5; ++d) {
                    float df = f[px][d] - ta[d][u];
                    dsq += df * df;
                }
                if (dsq < dd[px][4]) {
                    dd[px][4] = dsq; id[px][4] = j;
#pragma unroll
                    for (int s = 4; s > 0; --s) {
                        if (dd[px][s] < dd[px][s - 1]) {
                            float tv = dd[px][s]; dd[px][s] = dd[px][s - 1]; dd[px][s - 1] = tv;
                            int   ti = id[px][s]; id[px][s] = id[px][s - 1]; id[px][s - 1] = ti;
                        }
                    }
                }
            }
        }
    }

#pragma unroll
    for (int px = 0; px < 2; ++px) {
        int p = base + px * 256 + t;
        int cnt = 0;
#pragma unroll
        for (int s = 0; s < 5; ++s) cnt += (id[px][s] < NPC);
        bool seg = (cnt >= 2);   // probas = cnt/5 >= 0.3
        float* o = out + (size_t)b * NPIX * 3 + (size_t)p * 3;
        o[0] = seg ? v[px][0] : 0.0f;
        o[1] = seg ? v[px][1] : 0.0f;
        o[2] = seg ? v[px][2] : 0.0f;
    }
}

// ---------------------------------------------------------------------------
// host: derive JAX keys — partitionable threefry (default since JAX 0.4.36)
// ---------------------------------------------------------------------------
static void compute_keys(Keys& kp)
{
    for (int b = 0; b < NIMG; ++b) {
        unsigned int ik0, ik1;
        threefry2x32(0u, 42u, 0u, (unsigned int)b, ik0, ik1);   // split(key(42),32)[b]
        unsigned int f0, f1, g0, g1;
        threefry2x32(ik0, ik1, 0u, 0u, f0, f1);                 // split(imgkey)[0] = k_fg
        threefry2x32(ik0, ik1, 0u, 1u, g0, g1);                 // split(imgkey)[1] = k_bg
        kp.k[b][0] = f0; kp.k[b][1] = f1;
        kp.k[b][2] = g0; kp.k[b][3] = g1;
    }
}

extern "C" void kernel_launch(void* const* d_in, const int* in_sizes, int n_in,
                              void* d_out, int out_size)
{
    const float* img = (const float*)d_in[0];
    float* out = (float*)d_out;
    (void)in_sizes; (void)n_in; (void)out_size;

    Keys kp;
    compute_keys(kp);

    k1_sample<<<NIMG, 1024>>>(img, kp);
    dim3 g2(NPIX / PXB, NIMG);
    k2_knn<<<g2, 256>>>(img, out);
}

// round 7
// speedup vs baseline: 1.9482x; 1.1183x over previous
#include <cuda_runtime.h>
#include <stdint.h>

#define HW    96
#define NPIX  9216          // 96*96
#define NIMG  32
#define NTRAIN 100
#define NPC   50
#define NPAD  52            // per-class padded train count (13 float4)
#define CAP   1024
#define PADV  1.0e18f

struct Keys { unsigned int k[NIMG][4]; };   // per image: kfg0,kfg1,kbg0,kbg1

// ---------------------------------------------------------------------------
// threefry2x32 (JAX-exact)
// ---------------------------------------------------------------------------
__host__ __device__ __forceinline__ void threefry2x32(
    unsigned int k0, unsigned int k1,
    unsigned int x0, unsigned int x1,
    unsigned int &o0, unsigned int &o1)
{
    unsigned int ks[3];
    ks[0] = k0; ks[1] = k1; ks[2] = k0 ^ k1 ^ 0x1BD11BDAu;
    x0 += ks[0]; x1 += ks[1];
    const int rot[8] = {13, 15, 26, 6, 17, 29, 16, 24};
#pragma unroll
    for (int i = 0; i < 5; ++i) {
#pragma unroll
        for (int j = 0; j < 4; ++j) {
            int r = rot[(i & 1) * 4 + j];
            x0 += x1;
            x1 = (x1 << r) | (x1 >> (32 - r));
            x1 ^= x0;
        }
        x0 += ks[(i + 1) % 3];
        x1 += ks[(i + 2) % 3] + (unsigned int)(i + 1);
    }
    o0 = x0; o1 = x1;
}

// partitionable-mode 32-bit random word for flat index i (iota64: hi=0, lo=i)
__device__ __forceinline__ unsigned int tf_bits32(unsigned int k0, unsigned int k1,
                                                  unsigned int i)
{
    unsigned int r0, r1;
    threefry2x32(k0, k1, 0u, i, r0, r1);
    return r0 ^ r1;
}

__device__ __forceinline__ float bits_to_unit_float(unsigned int bits)
{
    unsigned int fb = (bits >> 9) | 0x3f800000u;
    return __uint_as_float(fb) - 1.0f;
}

__device__ __forceinline__ float clip01(float x)
{
    return fminf(fmaxf(x, 0.0f), 1.0f);
}

// ---------------------------------------------------------------------------
// scratch (no cudaMalloc allowed)
// ---------------------------------------------------------------------------
__device__ int    g_sel[NIMG][2][NPC];           // selected pixel indices
__device__ float4 g_tr4[NIMG][2][5][NPAD / 4];   // standardized train, padded SoA
__device__ float  g_mean[NIMG][5];
__device__ float  g_std[NIMG][5];

// ---------------------------------------------------------------------------
// Kernel 1: per-(image,class) sampling.  grid (NIMG, 2), 1024 thr.
// ---------------------------------------------------------------------------
__global__ __launch_bounds__(1024) void k1_sample(const float* __restrict__ img, Keys kp)
{
    const int b = blockIdx.x;
    const int pass = blockIdx.y;              // 0 = fg, 1 = bg
    const int t = threadIdx.x;
    const int lane = t & 31;
    const int warp = t >> 5;
    const float* im = img + (size_t)b * NPIX * 3;

    __shared__ float score[NPIX];             // 36 KB
    __shared__ int   hist[256];
    __shared__ int   scan[257];
    __shared__ int   cidx[CAP];
    __shared__ int   s_B, s_cnt;
    __shared__ float redv[32];
    __shared__ int   redi[32];
    __shared__ int   chmaxi[3];

    // ---- per-channel max of clipped image ----
    if (t < 3) chmaxi[t] = 0;
    if (t < 256) hist[t] = 0;
    if (t == 0) { s_B = -1; s_cnt = 0; }
    __syncthreads();
    float m0 = 0.f, m1 = 0.f, m2 = 0.f;
    for (int p = t; p < NPIX; p += 1024) {
        m0 = fmaxf(m0, clip01(im[p * 3 + 0] / 255.0f));
        m1 = fmaxf(m1, clip01(im[p * 3 + 1] / 255.0f));
        m2 = fmaxf(m2, clip01(im[p * 3 + 2] / 255.0f));
    }
    atomicMax(&chmaxi[0], __float_as_int(m0));
    atomicMax(&chmaxi[1], __float_as_int(m1));
    atomicMax(&chmaxi[2], __float_as_int(m2));
    __syncthreads();
    const float cm0 = __int_as_float(chmaxi[0]);
    const float cm1 = __int_as_float(chmaxi[1]);
    const float cm2 = __int_as_float(chmaxi[2]);

    const unsigned int kk0 = kp.k[b][pass * 2 + 0];
    const unsigned int kk1 = kp.k[b][pass * 2 + 1];

    // ---- scores + histogram (scores uniform in [0,1) for valid, -1 invalid)
    for (int p = t; p < NPIX; p += 1024) {
        unsigned int bits = tf_bits32(kk0, kk1, (unsigned int)p);
        float v0 = clip01(im[p * 3 + 0] / 255.0f);
        float v1 = clip01(im[p * 3 + 1] / 255.0f);
        float v2 = clip01(im[p * 3 + 2] / 255.0f);
        float n0 = v0 / cm0, n1 = v1 / cm1, n2 = v2 / cm2;
        bool fg = (n0 > 0.f && n0 < 0.6f) ||
                  (n1 > 0.f && n1 < 0.6f) ||
                  (n2 > 0.f && n2 < 0.6f);
        bool valid = pass ? (!fg) : fg;
        float sc = valid ? bits_to_unit_float(bits) : -1.0f;
        score[p] = sc;
        if (valid) {
            int bin = min((int)(sc * 256.0f), 255);
            atomicAdd(&hist[bin], 1);
        }
    }
    __syncthreads();

    // ---- parallel suffix scan over hist (Hillis-Steele, 8 steps) ----
    if (t < 256) scan[t] = hist[t];
    __syncthreads();
#pragma unroll
    for (int off = 1; off < 256; off <<= 1) {
        int v = 0;
        if (t < 256 && t + off < 256) v = scan[t + off];
        __syncthreads();
        if (t < 256) scan[t] += v;
        __syncthreads();
    }
    // threshold bin: largest B with suffix(B) >= NPC
    if (t < 256 && scan[t] >= NPC && (t == 255 || scan[t + 1] < NPC)) s_B = t;
    __syncthreads();
    const int B = s_B;

    bool fast_ok = false;
    if (B >= 0) {
        // collect candidates with bin >= B
        for (int p = t; p < NPIX; p += 1024) {
            float v = score[p];
            if (v >= 0.0f) {
                int bin = min((int)(v * 256.0f), 255);
                if (bin >= B) {
                    int pos = atomicAdd(&s_cnt, 1);
                    if (pos < CAP) cidx[pos] = p;
                }
            }
        }
        __syncthreads();
        const int cnt = s_cnt;
        if (cnt <= CAP) {
            fast_ok = true;
            if (t < cnt) {
                int myi = cidx[t];
                float myv = score[myi];
                int rank = 0;
                for (int j = 0; j < cnt; ++j) {
                    int oj = cidx[j];
                    float ov = score[oj];
                    rank += (ov > myv) || (ov == myv && oj < myi);
                }
                if (rank < NPC) g_sel[b][pass][rank] = myi;
            }
        }
        __syncthreads();
    }

    if (!fast_ok) {
        // fallback: 50 serialized argmax passes (deterministic safety net)
        for (int s = 0; s < NPC; ++s) {
            float bv = -3.0f; int bi = NPIX;
            for (int p = t; p < NPIX; p += 1024) {
                float v = score[p];
                if (v > bv) { bv = v; bi = p; }
            }
#pragma unroll
            for (int off = 16; off > 0; off >>= 1) {
                float ov = __shfl_down_sync(0xffffffffu, bv, off);
                int   oi = __shfl_down_sync(0xffffffffu, bi, off);
                if (ov > bv || (ov == bv && oi < bi)) { bv = ov; bi = oi; }
            }
            if (lane == 0) { redv[warp] = bv; redi[warp] = bi; }
            __syncthreads();
            if (warp == 0) {
                bv = redv[lane]; bi = redi[lane];
#pragma unroll
                for (int off = 16; off > 0; off >>= 1) {
                    float ov = __shfl_down_sync(0xffffffffu, bv, off);
                    int   oi = __shfl_down_sync(0xffffffffu, bi, off);
                    if (ov > bv || (ov == bv && oi < bi)) { bv = ov; bi = oi; }
                }
                if (lane == 0) { g_sel[b][pass][s] = bi; score[bi] = -2.0f; }
            }
            __syncthreads();
        }
    }
}

// ---------------------------------------------------------------------------
// Kernel 1b: train-set build + standardize.  grid NIMG, 256 thr.
// ---------------------------------------------------------------------------
__global__ __launch_bounds__(256) void k1b_build(const float* __restrict__ img)
{
    const int b = blockIdx.x;
    const int t = threadIdx.x;
    const float* im = img + (size_t)b * NPIX * 3;

    __shared__ float trf[NTRAIN][5];
    __shared__ float smean[5], sstd[5];

    if (t < NTRAIN) {
        int idx = g_sel[b][t / NPC][t % NPC];
        int ii = idx / HW, jj = idx % HW;
        trf[t][0] = clip01(im[idx * 3 + 0] / 255.0f) / 255.0f;
        trf[t][1] = clip01(im[idx * 3 + 1] / 255.0f) / 255.0f;
        trf[t][2] = clip01(im[idx * 3 + 2] / 255.0f) / 255.0f;
        trf[t][3] = (float)ii / 96.0f * 100.0f;
        trf[t][4] = (float)jj / 96.0f * 100.0f;
    }
    __syncthreads();

    if (t < 5) {
        float s = 0.f;
        for (int j = 0; j < NTRAIN; ++j) s += trf[j][t];
        float mean = s / (float)NTRAIN;
        float s2 = 0.f;
        for (int j = 0; j < NTRAIN; ++j) {
            float d = trf[j][t] - mean;
            s2 += d * d;
        }
        float sd = sqrtf(s2 / (float)NTRAIN);
        smean[t] = mean; sstd[t] = sd;
        g_mean[b][t] = mean; g_std[b][t] = sd;
    }
    __syncthreads();

    // padded standardized SoA write: flat i -> cls=i/260, d=(i%260)/52, j=i%52
    float* gt = (float*)&g_tr4[b][0][0][0];
    for (int i = t; i < 2 * 5 * NPAD; i += 256) {
        int cls = i / (5 * NPAD);
        int r = i % (5 * NPAD);
        int d = r / NPAD, j = r % NPAD;
        float v = (j < NPC) ? (trf[cls * NPC + j][d] - smean[d]) / sstd[d] : PADV;
        gt[i] = v;
    }
}

// ---------------------------------------------------------------------------
// Kernel 2: KNN classify + mask.  1 px/thread, index-free dual top-5 lists.
// ---------------------------------------------------------------------------
__global__ __launch_bounds__(256) void k2_knn(const float* __restrict__ img,
                                              float* __restrict__ out)
{
    const int b = blockIdx.y;
    const int t = threadIdx.x;
    const int p = blockIdx.x * 256 + t;

    __shared__ float4 trs4[2][5][NPAD / 4];   // 130 float4
    __shared__ float sm[5], ss[5];

    if (t < 130) {
        int cls = t / 65, r = t % 65;
        trs4[cls][r / 13][r % 13] = g_tr4[b][cls][r / 13][r % 13];
    }
    if (t >= 192 && t < 197)      sm[t - 192] = g_mean[b][t - 192];
    else if (t >= 224 && t < 229) ss[t - 224] = g_std[b][t - 224];
    __syncthreads();

    const float* im = img + (size_t)b * NPIX * 3;

    float v0 = clip01(im[p * 3 + 0] / 255.0f);
    float v1 = clip01(im[p * 3 + 1] / 255.0f);
    float v2 = clip01(im[p * 3 + 2] / 255.0f);

    float f[5];
    f[0] = (v0 / 255.0f - sm[0]) / ss[0];
    f[1] = (v1 / 255.0f - sm[1]) / ss[1];
    f[2] = (v2 / 255.0f - sm[2]) / ss[2];
    f[3] = ((float)(p / HW) / 96.0f * 100.0f - sm[3]) / ss[3];
    f[4] = ((float)(p % HW) / 96.0f * 100.0f - sm[4]) / ss[4];

    float dfg[5], dbg[5];
#pragma unroll
    for (int s = 0; s < 5; ++s) { dfg[s] = 1e30f; dbg[s] = 1e30f; }

#pragma unroll
    for (int cls = 0; cls < 2; ++cls) {
        float* L = cls ? dbg : dfg;
        for (int jb = 0; jb < NPAD / 4; ++jb) {
            float ta[5][4];
#pragma unroll
            for (int d = 0; d < 5; ++d)
                *(float4*)ta[d] = trs4[cls][d][jb];
#pragma unroll
            for (int u = 0; u < 4; ++u) {
                float dsq = 0.f;
#pragma unroll
                for (int d = 0; d < 5; ++d) {
                    float df = f[d] - ta[d][u];
                    dsq += df * df;
                }
                if (dsq < L[4]) {
                    L[4] = dsq;
#pragma unroll
                    for (int s = 4; s > 0; --s) {
                        if (L[s] < L[s - 1]) {
                            float tv = L[s]; L[s] = L[s - 1]; L[s - 1] = tv;
                        }
                    }
                }
            }
        }
    }

    // merge count: #fg among global top-5; fg wins ties (lower index)
    int cnt = 0, a = 0, bq = 0;
#pragma unroll
    for (int s = 0; s < 5; ++s) {
        if (dfg[a] <= dbg[bq]) { ++cnt; ++a; } else { ++bq; }
    }
    bool seg = (cnt >= 2);   // probas = cnt/5 >= 0.3

    float* o = out + (size_t)b * NPIX * 3 + (size_t)p * 3;
    o[0] = seg ? v0 : 0.0f;
    o[1] = seg ? v1 : 0.0f;
    o[2] = seg ? v2 : 0.0f;
}

// ---------------------------------------------------------------------------
// host: derive JAX keys — partitionable threefry (default since JAX 0.4.36)
// ---------------------------------------------------------------------------
static void compute_keys(Keys& kp)
{
    for (int b = 0; b < NIMG; ++b) {
        unsigned int ik0, ik1;
        threefry2x32(0u, 42u, 0u, (unsigned int)b, ik0, ik1);   // split(key(42),32)[b]
        unsigned int f0, f1, g0, g1;
        threefry2x32(ik0, ik1, 0u, 0u, f0, f1);                 // split(imgkey)[0] = k_fg
        threefry2x32(ik0, ik1, 0u, 1u, g0, g1);                 // split(imgkey)[1] = k_bg
        kp.k[b][0] = f0; kp.k[b][1] = f1;
        kp.k[b][2] = g0; kp.k[b][3] = g1;
    }
}

extern "C" void kernel_launch(void* const* d_in, const int* in_sizes, int n_in,
                              void* d_out, int out_size)
{
    const float* img = (const float*)d_in[0];
    float* out = (float*)d_out;
    (void)in_sizes; (void)n_in; (void)out_size;

    Keys kp;
    compute_keys(kp);

    dim3 g1(NIMG, 2);
    k1_sample<<<g1, 1024>>>(img, kp);
    k1b_build<<<NIMG, 256>>>(img);
    dim3 g2(NPIX / 256, NIMG);
    k2_knn<<<g2, 256>>>(img, out);
}

// round 9
// speedup vs baseline: 2.0055x; 1.0294x over previous
#include <cuda_runtime.h>
#include <stdint.h>

#define HW    96
#define NPIX  9216          // 96*96
#define NIMG  32
#define NTRAIN 100
#define NPC   50
#define NPAD  52            // per-class padded train count (26 pairs)
#define NPAIR 26
#define CAP   1024
#define PADV  1.0e18f

struct Keys { unsigned int k[NIMG][4]; };   // per image: kfg0,kfg1,kbg0,kbg1

// ---------------------------------------------------------------------------
// packed f32x2 helpers (sm_103a: two fp32 lanes per FMA-pipe op, rn rounding)
// ---------------------------------------------------------------------------
__device__ __forceinline__ unsigned long long pk2(float lo, float hi)
{
    unsigned long long o;
    asm("mov.b64 %0, {%1, %2};" : "=l"(o) : "f"(lo), "f"(hi));
    return o;
}
__device__ __forceinline__ void upk2(float &lo, float &hi, unsigned long long v)
{
    asm("mov.b64 {%0, %1}, %2;" : "=f"(lo), "=f"(hi) : "l"(v));
}
__device__ __forceinline__ unsigned long long add2(unsigned long long a, unsigned long long b)
{
    unsigned long long o;
    asm("add.rn.f32x2 %0, %1, %2;" : "=l"(o) : "l"(a), "l"(b));
    return o;
}
__device__ __forceinline__ unsigned long long mul2(unsigned long long a, unsigned long long b)
{
    unsigned long long o;
    asm("mul.rn.f32x2 %0, %1, %2;" : "=l"(o) : "l"(a), "l"(b));
    return o;
}
__device__ __forceinline__ unsigned long long fma2(unsigned long long a, unsigned long long b,
                                                   unsigned long long c)
{
    unsigned long long o;
    asm("fma.rn.f32x2 %0, %1, %2, %3;" : "=l"(o) : "l"(a), "l"(b), "l"(c));
    return o;
}

// ---------------------------------------------------------------------------
// threefry2x32 (JAX-exact)
// ---------------------------------------------------------------------------
__host__ __device__ __forceinline__ void threefry2x32(
    unsigned int k0, unsigned int k1,
    unsigned int x0, unsigned int x1,
    unsigned int &o0, unsigned int &o1)
{
    unsigned int ks[3];
    ks[0] = k0; ks[1] = k1; ks[2] = k0 ^ k1 ^ 0x1BD11BDAu;
    x0 += ks[0]; x1 += ks[1];
    const int rot[8] = {13, 15, 26, 6, 17, 29, 16, 24};
#pragma unroll
    for (int i = 0; i < 5; ++i) {
#pragma unroll
        for (int j = 0; j < 4; ++j) {
            int r = rot[(i & 1) * 4 + j];
            x0 += x1;
            x1 = (x1 << r) | (x1 >> (32 - r));
            x1 ^= x0;
        }
        x0 += ks[(i + 1) % 3];
        x1 += ks[(i + 2) % 3] + (unsigned int)(i + 1);
    }
    o0 = x0; o1 = x1;
}

// partitionable-mode 32-bit random word for flat index i (iota64: hi=0, lo=i)
__device__ __forceinline__ unsigned int tf_bits32(unsigned int k0, unsigned int k1,
                                                  unsigned int i)
{
    unsigned int r0, r1;
    threefry2x32(k0, k1, 0u, i, r0, r1);
    return r0 ^ r1;
}

__device__ __forceinline__ float bits_to_unit_float(unsigned int bits)
{
    unsigned int fb = (bits >> 9) | 0x3f800000u;
    return __uint_as_float(fb) - 1.0f;
}

__device__ __forceinline__ float clip01(float x)
{
    return fminf(fmaxf(x, 0.0f), 1.0f);
}

// ---------------------------------------------------------------------------
// scratch (no cudaMalloc allowed)
// ---------------------------------------------------------------------------
__device__ int                g_sel[NIMG][2][NPC];
__device__ unsigned long long g_tr2[NIMG][2][5][NPAIR];  // NEGATED std. train pairs
__device__ float              g_mean[NIMG][5];
__device__ float              g_std[NIMG][5];

// ---------------------------------------------------------------------------
// Kernel 1: per-(image,class) sampling.  grid (NIMG, 2), 1024 thr.
// ---------------------------------------------------------------------------
__global__ __launch_bounds__(1024) void k1_sample(const float* __restrict__ img, Keys kp)
{
    const int b = blockIdx.x;
    const int pass = blockIdx.y;              // 0 = fg, 1 = bg
    const int t = threadIdx.x;
    const int lane = t & 31;
    const int warp = t >> 5;
    const float* im = img + (size_t)b * NPIX * 3;

    __shared__ float score[NPIX];             // 36 KB
    __shared__ int   hist[256];
    __shared__ int   scan[257];
    __shared__ int   cidx[CAP];
    __shared__ int   s_B, s_cnt;
    __shared__ float redv[32];
    __shared__ int   redi[32];
    __shared__ int   chmaxi[3];

    if (t < 3) chmaxi[t] = 0;
    if (t < 256) hist[t] = 0;
    if (t == 0) { s_B = -1; s_cnt = 0; }
    __syncthreads();
    float m0 = 0.f, m1 = 0.f, m2 = 0.f;
    for (int p = t; p < NPIX; p += 1024) {
        m0 = fmaxf(m0, clip01(im[p * 3 + 0] / 255.0f));
        m1 = fmaxf(m1, clip01(im[p * 3 + 1] / 255.0f));
        m2 = fmaxf(m2, clip01(im[p * 3 + 2] / 255.0f));
    }
    atomicMax(&chmaxi[0], __float_as_int(m0));
    atomicMax(&chmaxi[1], __float_as_int(m1));
    atomicMax(&chmaxi[2], __float_as_int(m2));
    __syncthreads();
    const float cm0 = __int_as_float(chmaxi[0]);
    const float cm1 = __int_as_float(chmaxi[1]);
    const float cm2 = __int_as_float(chmaxi[2]);

    const unsigned int kk0 = kp.k[b][pass * 2 + 0];
    const unsigned int kk1 = kp.k[b][pass * 2 + 1];

    for (int p = t; p < NPIX; p += 1024) {
        unsigned int bits = tf_bits32(kk0, kk1, (unsigned int)p);
        float v0 = clip01(im[p * 3 + 0] / 255.0f);
        float v1 = clip01(im[p * 3 + 1] / 255.0f);
        float v2 = clip01(im[p * 3 + 2] / 255.0f);
        float n0 = v0 / cm0, n1 = v1 / cm1, n2 = v2 / cm2;
        bool fg = (n0 > 0.f && n0 < 0.6f) ||
                  (n1 > 0.f && n1 < 0.6f) ||
                  (n2 > 0.f && n2 < 0.6f);
        bool valid = pass ? (!fg) : fg;
        float sc = valid ? bits_to_unit_float(bits) : -1.0f;
        score[p] = sc;
        if (valid) {
            int bin = min((int)(sc * 256.0f), 255);
            atomicAdd(&hist[bin], 1);
        }
    }
    __syncthreads();

    // parallel suffix scan over hist (Hillis-Steele, 8 steps)
    if (t < 256) scan[t] = hist[t];
    __syncthreads();
#pragma unroll
    for (int off = 1; off < 256; off <<= 1) {
        int v = 0;
        if (t < 256 && t + off < 256) v = scan[t + off];
        __syncthreads();
        if (t < 256) scan[t] += v;
        __syncthreads();
    }
    if (t < 256 && scan[t] >= NPC && (t == 255 || scan[t + 1] < NPC)) s_B = t;
    __syncthreads();
    const int B = s_B;

    bool fast_ok = false;
    if (B >= 0) {
        for (int p = t; p < NPIX; p += 1024) {
            float v = score[p];
            if (v >= 0.0f) {
                int bin = min((int)(v * 256.0f), 255);
                if (bin >= B) {
                    int pos = atomicAdd(&s_cnt, 1);
                    if (pos < CAP) cidx[pos] = p;
                }
            }
        }
        __syncthreads();
        const int cnt = s_cnt;
        if (cnt <= CAP) {
            fast_ok = true;
            if (t < cnt) {
                int myi = cidx[t];
                float myv = score[myi];
                int rank = 0;
                for (int j = 0; j < cnt; ++j) {
                    int oj = cidx[j];
                    float ov = score[oj];
                    rank += (ov > myv) || (ov == myv && oj < myi);
                }
                if (rank < NPC) g_sel[b][pass][rank] = myi;
            }
        }
        __syncthreads();
    }

    if (!fast_ok) {
        for (int s = 0; s < NPC; ++s) {
            float bv = -3.0f; int bi = NPIX;
            for (int p = t; p < NPIX; p += 1024) {
                float v = score[p];
                if (v > bv) { bv = v; bi = p; }
            }
#pragma unroll
            for (int off = 16; off > 0; off >>= 1) {
                float ov = __shfl_down_sync(0xffffffffu, bv, off);
                int   oi = __shfl_down_sync(0xffffffffu, bi, off);
                if (ov > bv || (ov == bv && oi < bi)) { bv = ov; bi = oi; }
            }
            if (lane == 0) { redv[warp] = bv; redi[warp] = bi; }
            __syncthreads();
            if (warp == 0) {
                bv = redv[lane]; bi = redi[lane];
#pragma unroll
                for (int off = 16; off > 0; off >>= 1) {
                    float ov = __shfl_down_sync(0xffffffffu, bv, off);
                    int   oi = __shfl_down_sync(0xffffffffu, bi, off);
                    if (ov > bv || (ov == bv && oi < bi)) { bv = ov; bi = oi; }
                }
                if (lane == 0) { g_sel[b][pass][s] = bi; score[bi] = -2.0f; }
            }
            __syncthreads();
        }
    }
}

// ---------------------------------------------------------------------------
// Kernel 1b: train-set build + standardize + negated pair-packed write.
// ---------------------------------------------------------------------------
__global__ __launch_bounds__(256) void k1b_build(const float* __restrict__ img)
{
    const int b = blockIdx.x;
    const int t = threadIdx.x;
    const float* im = img + (size_t)b * NPIX * 3;

    __shared__ float trf[NTRAIN][5];
    __shared__ float smean[5], sstd[5];

    if (t < NTRAIN) {
        int idx = g_sel[b][t / NPC][t % NPC];
        int ii = idx / HW, jj = idx % HW;
        trf[t][0] = clip01(im[idx * 3 + 0] / 255.0f) / 255.0f;
        trf[t][1] = clip01(im[idx * 3 + 1] / 255.0f) / 255.0f;
        trf[t][2] = clip01(im[idx * 3 + 2] / 255.0f) / 255.0f;
        trf[t][3] = (float)ii / 96.0f * 100.0f;
        trf[t][4] = (float)jj / 96.0f * 100.0f;
    }
    __syncthreads();

    if (t < 5) {
        float s = 0.f;
        for (int j = 0; j < NTRAIN; ++j) s += trf[j][t];
        float mean = s / (float)NTRAIN;
        float s2 = 0.f;
        for (int j = 0; j < NTRAIN; ++j) {
            float d = trf[j][t] - mean;
            s2 += d * d;
        }
        float sd = sqrtf(s2 / (float)NTRAIN);
        smean[t] = mean; sstd[t] = sd;
        g_mean[b][t] = mean; g_std[b][t] = sd;
    }
    __syncthreads();

    // negated standardized pairs: flat i -> cls, d, q ; j0=2q, j1=2q+1
    for (int i = t; i < 2 * 5 * NPAIR; i += 256) {
        int cls = i / (5 * NPAIR);
        int r = i % (5 * NPAIR);
        int d = r / NPAIR, q = r % NPAIR;
        int j0 = 2 * q, j1 = 2 * q + 1;
        float a = (j0 < NPC) ? -((trf[cls * NPC + j0][d] - smean[d]) / sstd[d]) : -PADV;
        float c = (j1 < NPC) ? -((trf[cls * NPC + j1][d] - smean[d]) / sstd[d]) : -PADV;
        unsigned int ua = __float_as_uint(a), uc = __float_as_uint(c);
        g_tr2[b][cls][d][q] = ((unsigned long long)uc << 32) | (unsigned long long)ua;
    }
}

// ---------------------------------------------------------------------------
// Kernel 2: KNN classify + mask.  1 px/thread, f32x2 packed (2 pts / instr).
// Per-lane arithmetic identical to scalar: d=f+(-t); dsq chain fma d0..d4.
// ---------------------------------------------------------------------------
__global__ __launch_bounds__(256) void k2_knn(const float* __restrict__ img,
                                              float* __restrict__ out)
{
    const int b = blockIdx.y;
    const int t = threadIdx.x;
    const int p = blockIdx.x * 256 + t;

    __shared__ unsigned long long sneg[2][5][NPAIR];   // 260 u64
    __shared__ float sm[5], ss[5];

    // FIX (R8): strided loop covers all 260 entries with 256 threads;
    // mean/std loaded by provably-in-range low threads.
    {
        unsigned long long* dst = &sneg[0][0][0];
        const unsigned long long* src = &g_tr2[b][0][0][0];
        for (int i = t; i < 2 * 5 * NPAIR; i += 256) dst[i] = src[i];
    }
    if (t < 5)           sm[t] = g_mean[b][t];
    else if (t < 10)     ss[t - 5] = g_std[b][t - 5];
    __syncthreads();

    const float* im = img + (size_t)b * NPIX * 3;

    float v0 = clip01(im[p * 3 + 0] / 255.0f);
    float v1 = clip01(im[p * 3 + 1] / 255.0f);
    float v2 = clip01(im[p * 3 + 2] / 255.0f);

    float f[5];
    f[0] = (v0 / 255.0f - sm[0]) / ss[0];
    f[1] = (v1 / 255.0f - sm[1]) / ss[1];
    f[2] = (v2 / 255.0f - sm[2]) / ss[2];
    f[3] = ((float)(p / HW) / 96.0f * 100.0f - sm[3]) / ss[3];
    f[4] = ((float)(p % HW) / 96.0f * 100.0f - sm[4]) / ss[4];

    unsigned long long f2[5];
#pragma unroll
    for (int d = 0; d < 5; ++d) f2[d] = pk2(f[d], f[d]);

    float dfg[5], dbg[5];
#pragma unroll
    for (int s = 0; s < 5; ++s) { dfg[s] = 1e38f; dbg[s] = 1e38f; }

#pragma unroll
    for (int cls = 0; cls < 2; ++cls) {
        float* L = cls ? dbg : dfg;
#pragma unroll 2
        for (int q = 0; q < NPAIR; ++q) {
            unsigned long long d0 = add2(f2[0], sneg[cls][0][q]);
            unsigned long long d1 = add2(f2[1], sneg[cls][1][q]);
            unsigned long long d2 = add2(f2[2], sneg[cls][2][q]);
            unsigned long long d3 = add2(f2[3], sneg[cls][3][q]);
            unsigned long long d4 = add2(f2[4], sneg[cls][4][q]);
            unsigned long long acc = mul2(d0, d0);
            acc = fma2(d1, d1, acc);
            acc = fma2(d2, d2, acc);
            acc = fma2(d3, d3, acc);
            acc = fma2(d4, d4, acc);
            float lo, hi;
            upk2(lo, hi, acc);
            if (lo < L[4]) {
                L[4] = lo;
#pragma unroll
                for (int s = 4; s > 0; --s)
                    if (L[s] < L[s - 1]) { float tv = L[s]; L[s] = L[s - 1]; L[s - 1] = tv; }
            }
            if (hi < L[4]) {
                L[4] = hi;
#pragma unroll
                for (int s = 4; s > 0; --s)
                    if (L[s] < L[s - 1]) { float tv = L[s]; L[s] = L[s - 1]; L[s - 1] = tv; }
            }
        }
    }

    // merge count: #fg among global top-5; fg wins ties (lower train index)
    int cnt = 0, a = 0, bq = 0;
#pragma unroll
    for (int s = 0; s < 5; ++s) {
        if (dfg[a] <= dbg[bq]) { ++cnt; ++a; } else { ++bq; }
    }
    bool seg = (cnt >= 2);   // probas = cnt/5 >= 0.3

    float* o = out + (size_t)b * NPIX * 3 + (size_t)p * 3;
    o[0] = seg ? v0 : 0.0f;
    o[1] = seg ? v1 : 0.0f;
    o[2] = seg ? v2 : 0.0f;
}

// ---------------------------------------------------------------------------
// host: derive JAX keys — partitionable threefry (default since JAX 0.4.36)
// ---------------------------------------------------------------------------
static void compute_keys(Keys& kp)
{
    for (int b = 0; b < NIMG; ++b) {
        unsigned int ik0, ik1;
        threefry2x32(0u, 42u, 0u, (unsigned int)b, ik0, ik1);   // split(key(42),32)[b]
        unsigned int f0, f1, g0, g1;
        threefry2x32(ik0, ik1, 0u, 0u, f0, f1);                 // split(imgkey)[0] = k_fg
        threefry2x32(ik0, ik1, 0u, 1u, g0, g1);                 // split(imgkey)[1] = k_bg
        kp.k[b][0] = f0; kp.k[b][1] = f1;
        kp.k[b][2] = g0; kp.k[b][3] = g1;
    }
}

extern "C" void kernel_launch(void* const* d_in, const int* in_sizes, int n_in,
                              void* d_out, int out_size)
{
    const float* img = (const float*)d_in[0];
    float* out = (float*)d_out;
    (void)in_sizes; (void)n_in; (void)out_size;

    Keys kp;
    compute_keys(kp);

    dim3 g1(NIMG, 2);
    k1_sample<<<g1, 1024>>>(img, kp);
    k1b_build<<<NIMG, 256>>>(img);
    dim3 g2(NPIX / 256, NIMG);
    k2_knn<<<g2, 256>>>(img, out);
}

// round 10
// speedup vs baseline: 2.6050x; 1.2989x over previous
#include <cuda_runtime.h>
#include <stdint.h>

#define HW    96
#define NPIX  9216          // 96*96
#define NIMG  32
#define NTRAIN 100
#define NPC   50
#define NPAD  52            // per-class padded train count (26 pairs)
#define NPAIR 26
#define CAP   1024
#define PADV  1.0e18f

struct Keys { unsigned int k[NIMG][4]; };   // per image: kfg0,kfg1,kbg0,kbg1

// ---------------------------------------------------------------------------
// packed f32x2 helpers (sm_103a: two fp32 lanes per FMA-pipe op, rn rounding)
// ---------------------------------------------------------------------------
__device__ __forceinline__ unsigned long long pk2(float lo, float hi)
{
    unsigned long long o;
    asm("mov.b64 %0, {%1, %2};" : "=l"(o) : "f"(lo), "f"(hi));
    return o;
}
__device__ __forceinline__ void upk2(float &lo, float &hi, unsigned long long v)
{
    asm("mov.b64 {%0, %1}, %2;" : "=f"(lo), "=f"(hi) : "l"(v));
}
__device__ __forceinline__ unsigned long long add2(unsigned long long a, unsigned long long b)
{
    unsigned long long o;
    asm("add.rn.f32x2 %0, %1, %2;" : "=l"(o) : "l"(a), "l"(b));
    return o;
}
__device__ __forceinline__ unsigned long long mul2(unsigned long long a, unsigned long long b)
{
    unsigned long long o;
    asm("mul.rn.f32x2 %0, %1, %2;" : "=l"(o) : "l"(a), "l"(b));
    return o;
}
__device__ __forceinline__ unsigned long long fma2(unsigned long long a, unsigned long long b,
                                                   unsigned long long c)
{
    unsigned long long o;
    asm("fma.rn.f32x2 %0, %1, %2, %3;" : "=l"(o) : "l"(a), "l"(b), "l"(c));
    return o;
}

// ---------------------------------------------------------------------------
// threefry2x32 (JAX-exact)
// ---------------------------------------------------------------------------
__host__ __device__ __forceinline__ void threefry2x32(
    unsigned int k0, unsigned int k1,
    unsigned int x0, unsigned int x1,
    unsigned int &o0, unsigned int &o1)
{
    unsigned int ks[3];
    ks[0] = k0; ks[1] = k1; ks[2] = k0 ^ k1 ^ 0x1BD11BDAu;
    x0 += ks[0]; x1 += ks[1];
    const int rot[8] = {13, 15, 26, 6, 17, 29, 16, 24};
#pragma unroll
    for (int i = 0; i < 5; ++i) {
#pragma unroll
        for (int j = 0; j < 4; ++j) {
            int r = rot[(i & 1) * 4 + j];
            x0 += x1;
            x1 = (x1 << r) | (x1 >> (32 - r));
            x1 ^= x0;
        }
        x0 += ks[(i + 1) % 3];
        x1 += ks[(i + 2) % 3] + (unsigned int)(i + 1);
    }
    o0 = x0; o1 = x1;
}

// partitionable-mode 32-bit random word for flat index i (iota64: hi=0, lo=i)
__device__ __forceinline__ unsigned int tf_bits32(unsigned int k0, unsigned int k1,
                                                  unsigned int i)
{
    unsigned int r0, r1;
    threefry2x32(k0, k1, 0u, i, r0, r1);
    return r0 ^ r1;
}

__device__ __forceinline__ float bits_to_unit_float(unsigned int bits)
{
    unsigned int fb = (bits >> 9) | 0x3f800000u;
    return __uint_as_float(fb) - 1.0f;
}

__device__ __forceinline__ float clip01(float x)
{
    return fminf(fmaxf(x, 0.0f), 1.0f);
}

// ---------------------------------------------------------------------------
// scratch (no cudaMalloc allowed)
// ---------------------------------------------------------------------------
__device__ int                g_sel[NIMG][2][NPC];
__device__ unsigned long long g_tr2[NIMG][2][5][NPAIR];  // NEGATED std. train pairs
__device__ float              g_mean[NIMG][5];
__device__ float              g_std[NIMG][5];

// ---------------------------------------------------------------------------
// Kernel 1: per-(image,class) sampling.  grid (NIMG, 2), 1024 thr.
// ---------------------------------------------------------------------------
__global__ __launch_bounds__(1024) void k1_sample(const float* __restrict__ img, Keys kp)
{
    const int b = blockIdx.x;
    const int pass = blockIdx.y;              // 0 = fg, 1 = bg
    const int t = threadIdx.x;
    const int lane = t & 31;
    const int warp = t >> 5;
    const float* im = img + (size_t)b * NPIX * 3;

    __shared__ float score[NPIX];             // 36 KB
    __shared__ int   hist[256];
    __shared__ int   scan[257];
    __shared__ int   cidx[CAP];
    __shared__ int   s_B, s_cnt;
    __shared__ float redv[32];
    __shared__ int   redi[32];
    __shared__ int   chmaxi[3];

    if (t < 3) chmaxi[t] = 0;
    if (t < 256) hist[t] = 0;
    if (t == 0) { s_B = -1; s_cnt = 0; }
    __syncthreads();
    float m0 = 0.f, m1 = 0.f, m2 = 0.f;
    for (int p = t; p < NPIX; p += 1024) {
        m0 = fmaxf(m0, clip01(im[p * 3 + 0] / 255.0f));
        m1 = fmaxf(m1, clip01(im[p * 3 + 1] / 255.0f));
        m2 = fmaxf(m2, clip01(im[p * 3 + 2] / 255.0f));
    }
    atomicMax(&chmaxi[0], __float_as_int(m0));
    atomicMax(&chmaxi[1], __float_as_int(m1));
    atomicMax(&chmaxi[2], __float_as_int(m2));
    __syncthreads();
    const float cm0 = __int_as_float(chmaxi[0]);
    const float cm1 = __int_as_float(chmaxi[1]);
    const float cm2 = __int_as_float(chmaxi[2]);

    const unsigned int kk0 = kp.k[b][pass * 2 + 0];
    const unsigned int kk1 = kp.k[b][pass * 2 + 1];

    for (int p = t; p < NPIX; p += 1024) {
        unsigned int bits = tf_bits32(kk0, kk1, (unsigned int)p);
        float v0 = clip01(im[p * 3 + 0] / 255.0f);
        float v1 = clip01(im[p * 3 + 1] / 255.0f);
        float v2 = clip01(im[p * 3 + 2] / 255.0f);
        float n0 = v0 / cm0, n1 = v1 / cm1, n2 = v2 / cm2;
        bool fg = (n0 > 0.f && n0 < 0.6f) ||
                  (n1 > 0.f && n1 < 0.6f) ||
                  (n2 > 0.f && n2 < 0.6f);
        bool valid = pass ? (!fg) : fg;
        float sc = valid ? bits_to_unit_float(bits) : -1.0f;
        score[p] = sc;
        if (valid) {
            int bin = min((int)(sc * 256.0f), 255);
            atomicAdd(&hist[bin], 1);
        }
    }
    __syncthreads();

    // parallel suffix scan over hist (Hillis-Steele, 8 steps)
    if (t < 256) scan[t] = hist[t];
    __syncthreads();
#pragma unroll
    for (int off = 1; off < 256; off <<= 1) {
        int v = 0;
        if (t < 256 && t + off < 256) v = scan[t + off];
        __syncthreads();
        if (t < 256) scan[t] += v;
        __syncthreads();
    }
    if (t < 256 && scan[t] >= NPC && (t == 255 || scan[t + 1] < NPC)) s_B = t;
    __syncthreads();
    const int B = s_B;

    bool fast_ok = false;
    if (B >= 0) {
        for (int p = t; p < NPIX; p += 1024) {
            float v = score[p];
            if (v >= 0.0f) {
                int bin = min((int)(v * 256.0f), 255);
                if (bin >= B) {
                    int pos = atomicAdd(&s_cnt, 1);
                    if (pos < CAP) cidx[pos] = p;
                }
            }
        }
        __syncthreads();
        const int cnt = s_cnt;
        if (cnt <= CAP) {
            fast_ok = true;
            if (t < cnt) {
                int myi = cidx[t];
                float myv = score[myi];
                int rank = 0;
                for (int j = 0; j < cnt; ++j) {
                    int oj = cidx[j];
                    float ov = score[oj];
                    rank += (ov > myv) || (ov == myv && oj < myi);
                }
                if (rank < NPC) g_sel[b][pass][rank] = myi;
            }
        }
        __syncthreads();
    }

    if (!fast_ok) {
        for (int s = 0; s < NPC; ++s) {
            float bv = -3.0f; int bi = NPIX;
            for (int p = t; p < NPIX; p += 1024) {
                float v = score[p];
                if (v > bv) { bv = v; bi = p; }
            }
#pragma unroll
            for (int off = 16; off > 0; off >>= 1) {
                float ov = __shfl_down_sync(0xffffffffu, bv, off);
                int   oi = __shfl_down_sync(0xffffffffu, bi, off);
                if (ov > bv || (ov == bv && oi < bi)) { bv = ov; bi = oi; }
            }
            if (lane == 0) { redv[warp] = bv; redi[warp] = bi; }
            __syncthreads();
            if (warp == 0) {
                bv = redv[lane]; bi = redi[lane];
#pragma unroll
                for (int off = 16; off > 0; off >>= 1) {
                    float ov = __shfl_down_sync(0xffffffffu, bv, off);
                    int   oi = __shfl_down_sync(0xffffffffu, bi, off);
                    if (ov > bv || (ov == bv && oi < bi)) { bv = ov; bi = oi; }
                }
                if (lane == 0) { g_sel[b][pass][s] = bi; score[bi] = -2.0f; }
            }
            __syncthreads();
        }
    }
}

// ---------------------------------------------------------------------------
// Kernel 1b: train-set build + standardize + negated pair-packed write.
// ---------------------------------------------------------------------------
__global__ __launch_bounds__(256) void k1b_build(const float* __restrict__ img)
{
    const int b = blockIdx.x;
    const int t = threadIdx.x;
    const float* im = img + (size_t)b * NPIX * 3;

    __shared__ float trf[NTRAIN][5];
    __shared__ float smean[5], sstd[5];

    if (t < NTRAIN) {
        int idx = g_sel[b][t / NPC][t % NPC];
        int ii = idx / HW, jj = idx % HW;
        trf[t][0] = clip01(im[idx * 3 + 0] / 255.0f) / 255.0f;
        trf[t][1] = clip01(im[idx * 3 + 1] / 255.0f) / 255.0f;
        trf[t][2] = clip01(im[idx * 3 + 2] / 255.0f) / 255.0f;
        trf[t][3] = (float)ii / 96.0f * 100.0f;
        trf[t][4] = (float)jj / 96.0f * 100.0f;
    }
    __syncthreads();

    if (t < 5) {
        float s = 0.f;
        for (int j = 0; j < NTRAIN; ++j) s += trf[j][t];
        float mean = s / (float)NTRAIN;
        float s2 = 0.f;
        for (int j = 0; j < NTRAIN; ++j) {
            float d = trf[j][t] - mean;
            s2 += d * d;
        }
        float sd = sqrtf(s2 / (float)NTRAIN);
        smean[t] = mean; sstd[t] = sd;
        g_mean[b][t] = mean; g_std[b][t] = sd;
    }
    __syncthreads();

    // negated standardized pairs: flat i -> cls, d, q ; j0=2q, j1=2q+1
    for (int i = t; i < 2 * 5 * NPAIR; i += 256) {
        int cls = i / (5 * NPAIR);
        int r = i % (5 * NPAIR);
        int d = r / NPAIR, q = r % NPAIR;
        int j0 = 2 * q, j1 = 2 * q + 1;
        float a = (j0 < NPC) ? -((trf[cls * NPC + j0][d] - smean[d]) / sstd[d]) : -PADV;
        float c = (j1 < NPC) ? -((trf[cls * NPC + j1][d] - smean[d]) / sstd[d]) : -PADV;
        unsigned int ua = __float_as_uint(a), uc = __float_as_uint(c);
        g_tr2[b][cls][d][q] = ((unsigned long long)uc << 32) | (unsigned long long)ua;
    }
}

// ---------------------------------------------------------------------------
// scan one class: top-5 smallest dsq kept in named scalar registers (no
// dynamically-indexed locals -> no LDL/STL). Sorted ascending L0<=..<=L4.
// ---------------------------------------------------------------------------
__device__ __forceinline__ void top5_ins(float v, float &L0, float &L1, float &L2,
                                         float &L3, float &L4)
{
    if (v < L4) {
        L4 = v;
        if (L4 < L3) { float tv = L3; L3 = L4; L4 = tv; }
        if (L3 < L2) { float tv = L2; L2 = L3; L3 = tv; }
        if (L2 < L1) { float tv = L1; L1 = L2; L2 = tv; }
        if (L1 < L0) { float tv = L0; L0 = L1; L1 = tv; }
    }
}

__device__ __forceinline__ void scan_class(
    const unsigned long long* __restrict__ tr,   // [5][NPAIR] flattened
    unsigned long long f20, unsigned long long f21, unsigned long long f22,
    unsigned long long f23, unsigned long long f24,
    float &L0, float &L1, float &L2, float &L3, float &L4)
{
#pragma unroll 2
    for (int q = 0; q < NPAIR; ++q) {
        unsigned long long d0 = add2(f20, tr[0 * NPAIR + q]);
        unsigned long long d1 = add2(f21, tr[1 * NPAIR + q]);
        unsigned long long d2 = add2(f22, tr[2 * NPAIR + q]);
        unsigned long long d3 = add2(f23, tr[3 * NPAIR + q]);
        unsigned long long d4 = add2(f24, tr[4 * NPAIR + q]);
        unsigned long long acc = mul2(d0, d0);
        acc = fma2(d1, d1, acc);
        acc = fma2(d2, d2, acc);
        acc = fma2(d3, d3, acc);
        acc = fma2(d4, d4, acc);
        float lo, hi;
        upk2(lo, hi, acc);
        top5_ins(lo, L0, L1, L2, L3, L4);
        top5_ins(hi, L0, L1, L2, L3, L4);
    }
}

// ---------------------------------------------------------------------------
// Kernel 2: KNN classify + mask.  1 px/thread, f32x2, register-only top-5.
// ---------------------------------------------------------------------------
__global__ __launch_bounds__(256) void k2_knn(const float* __restrict__ img,
                                              float* __restrict__ out)
{
    const int b = blockIdx.y;
    const int t = threadIdx.x;
    const int p = blockIdx.x * 256 + t;

    __shared__ unsigned long long sneg[2 * 5 * NPAIR];   // 260 u64
    __shared__ float sm[5], ss[5];

    {
        const unsigned long long* src = &g_tr2[b][0][0][0];
        for (int i = t; i < 2 * 5 * NPAIR; i += 256) sneg[i] = src[i];
    }
    if (t < 5)           sm[t] = g_mean[b][t];
    else if (t < 10)     ss[t - 5] = g_std[b][t - 5];
    __syncthreads();

    const float* im = img + (size_t)b * NPIX * 3;

    float v0 = clip01(im[p * 3 + 0] / 255.0f);
    float v1 = clip01(im[p * 3 + 1] / 255.0f);
    float v2 = clip01(im[p * 3 + 2] / 255.0f);

    float f0 = (v0 / 255.0f - sm[0]) / ss[0];
    float f1 = (v1 / 255.0f - sm[1]) / ss[1];
    float f2v = (v2 / 255.0f - sm[2]) / ss[2];
    float f3 = ((float)(p / HW) / 96.0f * 100.0f - sm[3]) / ss[3];
    float f4 = ((float)(p % HW) / 96.0f * 100.0f - sm[4]) / ss[4];

    unsigned long long F0 = pk2(f0, f0), F1 = pk2(f1, f1), F2 = pk2(f2v, f2v),
                       F3 = pk2(f3, f3), F4 = pk2(f4, f4);

    float a0 = 1e38f, a1 = 1e38f, a2 = 1e38f, a3 = 1e38f, a4 = 1e38f;   // fg
    float b0 = 1e38f, b1 = 1e38f, b2 = 1e38f, b3 = 1e38f, b4 = 1e38f;   // bg

    scan_class(&sneg[0],          F0, F1, F2, F3, F4, a0, a1, a2, a3, a4);
    scan_class(&sneg[5 * NPAIR],  F0, F1, F2, F3, F4, b0, b1, b2, b3, b4);

    // fg count in merged top-5: a_i included iff i + #{b_j < a_i} <= 4
    // (strict < encodes fg-wins-ties: all fg train indices precede bg ones)
    int cnt = 0;
    {
        int l0 = (b0 < a0) + (b1 < a0) + (b2 < a0) + (b3 < a0) + (b4 < a0);
        int l1 = (b0 < a1) + (b1 < a1) + (b2 < a1) + (b3 < a1) + (b4 < a1);
        int l2 = (b0 < a2) + (b1 < a2) + (b2 < a2) + (b3 < a2) + (b4 < a2);
        int l3 = (b0 < a3) + (b1 < a3) + (b2 < a3) + (b3 < a3) + (b4 < a3);
        int l4 = (b0 < a4) + (b1 < a4) + (b2 < a4) + (b3 < a4) + (b4 < a4);
        cnt = (0 + l0 <= 4) + (1 + l1 <= 4) + (2 + l2 <= 4) + (3 + l3 <= 4) + (4 + l4 <= 4);
    }
    bool seg = (cnt >= 2);   // probas = cnt/5 >= 0.3

    float* o = out + (size_t)b * NPIX * 3 + (size_t)p * 3;
    o[0] = seg ? v0 : 0.0f;
    o[1] = seg ? v1 : 0.0f;
    o[2] = seg ? v2 : 0.0f;
}

// ---------------------------------------------------------------------------
// host: derive JAX keys — partitionable threefry (default since JAX 0.4.36)
// ---------------------------------------------------------------------------
static void compute_keys(Keys& kp)
{
    for (int b = 0; b < NIMG; ++b) {
        unsigned int ik0, ik1;
        threefry2x32(0u, 42u, 0u, (unsigned int)b, ik0, ik1);   // split(key(42),32)[b]
        unsigned int f0, f1, g0, g1;
        threefry2x32(ik0, ik1, 0u, 0u, f0, f1);                 // split(imgkey)[0] = k_fg
        threefry2x32(ik0, ik1, 0u, 1u, g0, g1);                 // split(imgkey)[1] = k_bg
        kp.k[b][0] = f0; kp.k[b][1] = f1;
        kp.k[b][2] = g0; kp.k[b][3] = g1;
    }
}

extern "C" void kernel_launch(void* const* d_in, const int* in_sizes, int n_in,
                              void* d_out, int out_size)
{
    const float* img = (const float*)d_in[0];
    float* out = (float*)d_out;
    (void)in_sizes; (void)n_in; (void)out_size;

    Keys kp;
    compute_keys(kp);

    dim3 g1(NIMG, 2);
    k1_sample<<<g1, 1024>>>(img, kp);
    k1b_build<<<NIMG, 256>>>(img);
    dim3 g2(NPIX / 256, NIMG);
    k2_knn<<<g2, 256>>>(img, out);
}

// round 11
// speedup vs baseline: 2.7152x; 1.0423x over previous
#include <cuda_runtime.h>
#include <stdint.h>

#define HW    96
#define NPIX  9216          // 96*96
#define NIMG  32
#define NTRAIN 100
#define NPC   50
#define NPAD  52            // per-class padded train count (26 pairs)
#define NPAIR 26
#define CAP   1024
#define PADV  1.0e18f

struct Keys { unsigned int k[NIMG][4]; };   // per image: kfg0,kfg1,kbg0,kbg1

// ---------------------------------------------------------------------------
// packed f32x2 helpers (sm_103a: two fp32 lanes per FMA-pipe op, rn rounding)
// ---------------------------------------------------------------------------
__device__ __forceinline__ unsigned long long pk2(float lo, float hi)
{
    unsigned long long o;
    asm("mov.b64 %0, {%1, %2};" : "=l"(o) : "f"(lo), "f"(hi));
    return o;
}
__device__ __forceinline__ void upk2(float &lo, float &hi, unsigned long long v)
{
    asm("mov.b64 {%0, %1}, %2;" : "=f"(lo), "=f"(hi) : "l"(v));
}
__device__ __forceinline__ unsigned long long add2(unsigned long long a, unsigned long long b)
{
    unsigned long long o;
    asm("add.rn.f32x2 %0, %1, %2;" : "=l"(o) : "l"(a), "l"(b));
    return o;
}
__device__ __forceinline__ unsigned long long mul2(unsigned long long a, unsigned long long b)
{
    unsigned long long o;
    asm("mul.rn.f32x2 %0, %1, %2;" : "=l"(o) : "l"(a), "l"(b));
    return o;
}
__device__ __forceinline__ unsigned long long fma2(unsigned long long a, unsigned long long b,
                                                   unsigned long long c)
{
    unsigned long long o;
    asm("fma.rn.f32x2 %0, %1, %2, %3;" : "=l"(o) : "l"(a), "l"(b), "l"(c));
    return o;
}

// ---------------------------------------------------------------------------
// threefry2x32 (JAX-exact)
// ---------------------------------------------------------------------------
__host__ __device__ __forceinline__ void threefry2x32(
    unsigned int k0, unsigned int k1,
    unsigned int x0, unsigned int x1,
    unsigned int &o0, unsigned int &o1)
{
    unsigned int ks[3];
    ks[0] = k0; ks[1] = k1; ks[2] = k0 ^ k1 ^ 0x1BD11BDAu;
    x0 += ks[0]; x1 += ks[1];
    const int rot[8] = {13, 15, 26, 6, 17, 29, 16, 24};
#pragma unroll
    for (int i = 0; i < 5; ++i) {
#pragma unroll
        for (int j = 0; j < 4; ++j) {
            int r = rot[(i & 1) * 4 + j];
            x0 += x1;
            x1 = (x1 << r) | (x1 >> (32 - r));
            x1 ^= x0;
        }
        x0 += ks[(i + 1) % 3];
        x1 += ks[(i + 2) % 3] + (unsigned int)(i + 1);
    }
    o0 = x0; o1 = x1;
}

// partitionable-mode 32-bit random word for flat index i (iota64: hi=0, lo=i)
__device__ __forceinline__ unsigned int tf_bits32(unsigned int k0, unsigned int k1,
                                                  unsigned int i)
{
    unsigned int r0, r1;
    threefry2x32(k0, k1, 0u, i, r0, r1);
    return r0 ^ r1;
}

__device__ __forceinline__ float bits_to_unit_float(unsigned int bits)
{
    unsigned int fb = (bits >> 9) | 0x3f800000u;
    return __uint_as_float(fb) - 1.0f;
}

__device__ __forceinline__ float clip01(float x)
{
    return fminf(fmaxf(x, 0.0f), 1.0f);
}

// ---------------------------------------------------------------------------
// scratch (no cudaMalloc allowed)
// ---------------------------------------------------------------------------
__device__ int                g_sel[NIMG][2][NPC];
__device__ unsigned long long g_tr2[NIMG][2][5][NPAIR];  // NEGATED std. train pairs
__device__ float              g_mean[NIMG][5];
__device__ float              g_std[NIMG][5];

// ---------------------------------------------------------------------------
// Kernel 1: per-(image,class) sampling.  grid (NIMG, 2), 1024 thr.
// Image read as 4-pixel groups (3x LDG.128); 4 independent threefry chains.
// ---------------------------------------------------------------------------
__global__ __launch_bounds__(1024) void k1_sample(const float* __restrict__ img, Keys kp)
{
    const int b = blockIdx.x;
    const int pass = blockIdx.y;              // 0 = fg, 1 = bg
    const int t = threadIdx.x;
    const int lane = t & 31;
    const int warp = t >> 5;
    const float* im = img + (size_t)b * NPIX * 3;
    const float4* im4 = (const float4*)im;    // 4 px = 3 float4

    __shared__ float score[NPIX];             // 36 KB
    __shared__ int   hist[256];
    __shared__ int   scan[257];
    __shared__ int   cidx[CAP];
    __shared__ int   s_B, s_cnt;
    __shared__ float redv[32];
    __shared__ int   redi[32];
    __shared__ int   chmaxi[3];

    if (t < 3) chmaxi[t] = 0;
    if (t < 256) hist[t] = 0;
    if (t == 0) { s_B = -1; s_cnt = 0; }
    __syncthreads();

    // ---- channel max over 4-px groups ----
    float m0 = 0.f, m1 = 0.f, m2 = 0.f;
    for (int g = t; g < NPIX / 4; g += 1024) {
        float4 A = im4[g * 3 + 0];
        float4 Bv = im4[g * 3 + 1];
        float4 C = im4[g * 3 + 2];
        m0 = fmaxf(m0, fmaxf(fmaxf(clip01(A.x / 255.0f), clip01(A.w / 255.0f)),
                             fmaxf(clip01(Bv.z / 255.0f), clip01(C.y / 255.0f))));
        m1 = fmaxf(m1, fmaxf(fmaxf(clip01(A.y / 255.0f), clip01(Bv.x / 255.0f)),
                             fmaxf(clip01(Bv.w / 255.0f), clip01(C.z / 255.0f))));
        m2 = fmaxf(m2, fmaxf(fmaxf(clip01(A.z / 255.0f), clip01(Bv.y / 255.0f)),
                             fmaxf(clip01(C.x / 255.0f), clip01(C.w / 255.0f))));
    }
    atomicMax(&chmaxi[0], __float_as_int(m0));
    atomicMax(&chmaxi[1], __float_as_int(m1));
    atomicMax(&chmaxi[2], __float_as_int(m2));
    __syncthreads();
    const float cm0 = __int_as_float(chmaxi[0]);
    const float cm1 = __int_as_float(chmaxi[1]);
    const float cm2 = __int_as_float(chmaxi[2]);

    const unsigned int kk0 = kp.k[b][pass * 2 + 0];
    const unsigned int kk1 = kp.k[b][pass * 2 + 1];

    // ---- scores + histogram, 4 px per iteration ----
    for (int g = t; g < NPIX / 4; g += 1024) {
        float4 A = im4[g * 3 + 0];
        float4 Bv = im4[g * 3 + 1];
        float4 C = im4[g * 3 + 2];
        float px0[4] = {A.x, A.w, Bv.z, C.y};
        float px1[4] = {A.y, Bv.x, Bv.w, C.z};
        float px2[4] = {A.z, Bv.y, C.x, C.w};
        float sc4[4];
#pragma unroll
        for (int u = 0; u < 4; ++u) {
            int p = 4 * g + u;
            unsigned int bits = tf_bits32(kk0, kk1, (unsigned int)p);
            float v0 = clip01(px0[u] / 255.0f);
            float v1 = clip01(px1[u] / 255.0f);
            float v2 = clip01(px2[u] / 255.0f);
            float n0 = v0 / cm0, n1 = v1 / cm1, n2 = v2 / cm2;
            bool fg = (n0 > 0.f && n0 < 0.6f) ||
                      (n1 > 0.f && n1 < 0.6f) ||
                      (n2 > 0.f && n2 < 0.6f);
            bool valid = pass ? (!fg) : fg;
            float sc = valid ? bits_to_unit_float(bits) : -1.0f;
            sc4[u] = sc;
            if (valid) {
                int bin = min((int)(sc * 256.0f), 255);
                atomicAdd(&hist[bin], 1);
            }
        }
        *(float4*)&score[4 * g] = make_float4(sc4[0], sc4[1], sc4[2], sc4[3]);
    }
    __syncthreads();

    // parallel suffix scan over hist (Hillis-Steele, 8 steps)
    if (t < 256) scan[t] = hist[t];
    __syncthreads();
#pragma unroll
    for (int off = 1; off < 256; off <<= 1) {
        int v = 0;
        if (t < 256 && t + off < 256) v = scan[t + off];
        __syncthreads();
        if (t < 256) scan[t] += v;
        __syncthreads();
    }
    if (t < 256 && scan[t] >= NPC && (t == 255 || scan[t + 1] < NPC)) s_B = t;
    __syncthreads();
    const int B = s_B;

    bool fast_ok = false;
    if (B >= 0) {
        for (int p = t; p < NPIX; p += 1024) {
            float v = score[p];
            if (v >= 0.0f) {
                int bin = min((int)(v * 256.0f), 255);
                if (bin >= B) {
                    int pos = atomicAdd(&s_cnt, 1);
                    if (pos < CAP) cidx[pos] = p;
                }
            }
        }
        __syncthreads();
        const int cnt = s_cnt;
        if (cnt <= CAP) {
            fast_ok = true;
            if (t < cnt) {
                int myi = cidx[t];
                float myv = score[myi];
                int rank = 0;
                for (int j = 0; j < cnt; ++j) {
                    int oj = cidx[j];
                    float ov = score[oj];
                    rank += (ov > myv) || (ov == myv && oj < myi);
                }
                if (rank < NPC) g_sel[b][pass][rank] = myi;
            }
        }
        __syncthreads();
    }

    if (!fast_ok) {
        for (int s = 0; s < NPC; ++s) {
            float bv = -3.0f; int bi = NPIX;
            for (int p = t; p < NPIX; p += 1024) {
                float v = score[p];
                if (v > bv) { bv = v; bi = p; }
            }
#pragma unroll
            for (int off = 16; off > 0; off >>= 1) {
                float ov = __shfl_down_sync(0xffffffffu, bv, off);
                int   oi = __shfl_down_sync(0xffffffffu, bi, off);
                if (ov > bv || (ov == bv && oi < bi)) { bv = ov; bi = oi; }
            }
            if (lane == 0) { redv[warp] = bv; redi[warp] = bi; }
            __syncthreads();
            if (warp == 0) {
                bv = redv[lane]; bi = redi[lane];
#pragma unroll
                for (int off = 16; off > 0; off >>= 1) {
                    float ov = __shfl_down_sync(0xffffffffu, bv, off);
                    int   oi = __shfl_down_sync(0xffffffffu, bi, off);
                    if (ov > bv || (ov == bv && oi < bi)) { bv = ov; bi = oi; }
                }
                if (lane == 0) { g_sel[b][pass][s] = bi; score[bi] = -2.0f; }
            }
            __syncthreads();
        }
    }
}

// ---------------------------------------------------------------------------
// Kernel 1b: train-set build + standardize + negated pair-packed write.
// ---------------------------------------------------------------------------
__global__ __launch_bounds__(256) void k1b_build(const float* __restrict__ img)
{
    const int b = blockIdx.x;
    const int t = threadIdx.x;
    const float* im = img + (size_t)b * NPIX * 3;

    __shared__ float trf[NTRAIN][5];
    __shared__ float smean[5], sstd[5];

    if (t < NTRAIN) {
        int idx = g_sel[b][t / NPC][t % NPC];
        int ii = idx / HW, jj = idx % HW;
        trf[t][0] = clip01(im[idx * 3 + 0] / 255.0f) / 255.0f;
        trf[t][1] = clip01(im[idx * 3 + 1] / 255.0f) / 255.0f;
        trf[t][2] = clip01(im[idx * 3 + 2] / 255.0f) / 255.0f;
        trf[t][3] = (float)ii / 96.0f * 100.0f;
        trf[t][4] = (float)jj / 96.0f * 100.0f;
    }
    __syncthreads();

    if (t < 5) {
        float s = 0.f;
        for (int j = 0; j < NTRAIN; ++j) s += trf[j][t];
        float mean = s / (float)NTRAIN;
        float s2 = 0.f;
        for (int j = 0; j < NTRAIN; ++j) {
            float d = trf[j][t] - mean;
            s2 += d * d;
        }
        float sd = sqrtf(s2 / (float)NTRAIN);
        smean[t] = mean; sstd[t] = sd;
        g_mean[b][t] = mean; g_std[b][t] = sd;
    }
    __syncthreads();

    // negated standardized pairs: flat i -> cls, d, q ; j0=2q, j1=2q+1
    for (int i = t; i < 2 * 5 * NPAIR; i += 256) {
        int cls = i / (5 * NPAIR);
        int r = i % (5 * NPAIR);
        int d = r / NPAIR, q = r % NPAIR;
        int j0 = 2 * q, j1 = 2 * q + 1;
        float a = (j0 < NPC) ? -((trf[cls * NPC + j0][d] - smean[d]) / sstd[d]) : -PADV;
        float c = (j1 < NPC) ? -((trf[cls * NPC + j1][d] - smean[d]) / sstd[d]) : -PADV;
        unsigned int ua = __float_as_uint(a), uc = __float_as_uint(c);
        g_tr2[b][cls][d][q] = ((unsigned long long)uc << 32) | (unsigned long long)ua;
    }
}

// ---------------------------------------------------------------------------
// top-5 (ascending L0<=..<=L4) insert, register-only.
// ---------------------------------------------------------------------------
__device__ __forceinline__ void top5_ins(float v, float &L0, float &L1, float &L2,
                                         float &L3, float &L4)
{
    if (v < L4) {
        L4 = v;
        if (L4 < L3) { float tv = L3; L3 = L4; L4 = tv; }
        if (L3 < L2) { float tv = L2; L2 = L3; L3 = tv; }
        if (L2 < L1) { float tv = L1; L1 = L2; L2 = tv; }
        if (L1 < L0) { float tv = L0; L0 = L1; L1 = tv; }
    }
}

// dsq for one packed pair vs pixel features; exact scalar order per lane.
__device__ __forceinline__ unsigned long long pair_dsq(
    unsigned long long t0, unsigned long long t1, unsigned long long t2,
    unsigned long long t3, unsigned long long t4,
    unsigned long long F0, unsigned long long F1, unsigned long long F2,
    unsigned long long F3, unsigned long long F4)
{
    unsigned long long d0 = add2(F0, t0);
    unsigned long long d1 = add2(F1, t1);
    unsigned long long d2 = add2(F2, t2);
    unsigned long long d3 = add2(F3, t3);
    unsigned long long d4 = add2(F4, t4);
    unsigned long long acc = mul2(d0, d0);
    acc = fma2(d1, d1, acc);
    acc = fma2(d2, d2, acc);
    acc = fma2(d3, d3, acc);
    acc = fma2(d4, d4, acc);
    return acc;
}

__device__ __forceinline__ void check_pair(unsigned long long acc,
                                           float &L0, float &L1, float &L2,
                                           float &L3, float &L4)
{
    float lo, hi;
    upk2(lo, hi, acc);
    if (fminf(lo, hi) < L4) {           // prefilter: common case 2 slots
        top5_ins(lo, L0, L1, L2, L3, L4);
        top5_ins(hi, L0, L1, L2, L3, L4);
    }
}

__device__ __forceinline__ void scan_class(
    const unsigned long long* __restrict__ tr,   // [5][NPAIR] flattened
    unsigned long long F0, unsigned long long F1, unsigned long long F2,
    unsigned long long F3, unsigned long long F4,
    float &L0, float &L1, float &L2, float &L3, float &L4)
{
    const ulonglong2* tr2 = (const ulonglong2*)tr;   // 13 per dim row
#pragma unroll
    for (int j = 0; j < NPAIR / 2; ++j) {
        ulonglong2 T0 = tr2[13 * 0 + j];
        ulonglong2 T1 = tr2[13 * 1 + j];
        ulonglong2 T2 = tr2[13 * 2 + j];
        ulonglong2 T3 = tr2[13 * 3 + j];
        ulonglong2 T4 = tr2[13 * 4 + j];
        unsigned long long accA = pair_dsq(T0.x, T1.x, T2.x, T3.x, T4.x,
                                           F0, F1, F2, F3, F4);
        unsigned long long accB = pair_dsq(T0.y, T1.y, T2.y, T3.y, T4.y,
                                           F0, F1, F2, F3, F4);
        check_pair(accA, L0, L1, L2, L3, L4);
        check_pair(accB, L0, L1, L2, L3, L4);
    }
}

// ---------------------------------------------------------------------------
// Kernel 2: KNN classify + mask.  1 px/thread, f32x2, register-only top-5.
// ---------------------------------------------------------------------------
__global__ __launch_bounds__(256) void k2_knn(const float* __restrict__ img,
                                              float* __restrict__ out)
{
    const int b = blockIdx.y;
    const int t = threadIdx.x;
    const int p = blockIdx.x * 256 + t;

    __shared__ __align__(16) unsigned long long sneg[2 * 5 * NPAIR];   // 260 u64
    __shared__ float sm[5], ss[5];

    {
        const unsigned long long* src = &g_tr2[b][0][0][0];
        for (int i = t; i < 2 * 5 * NPAIR; i += 256) sneg[i] = src[i];
    }
    if (t < 5)           sm[t] = g_mean[b][t];
    else if (t < 10)     ss[t - 5] = g_std[b][t - 5];
    __syncthreads();

    const float* im = img + (size_t)b * NPIX * 3;

    float v0 = clip01(im[p * 3 + 0] / 255.0f);
    float v1 = clip01(im[p * 3 + 1] / 255.0f);
    float v2 = clip01(im[p * 3 + 2] / 255.0f);

    float f0 = (v0 / 255.0f - sm[0]) / ss[0];
    float f1 = (v1 / 255.0f - sm[1]) / ss[1];
    float f2v = (v2 / 255.0f - sm[2]) / ss[2];
    float f3 = ((float)(p / HW) / 96.0f * 100.0f - sm[3]) / ss[3];
    float f4 = ((float)(p % HW) / 96.0f * 100.0f - sm[4]) / ss[4];

    unsigned long long F0 = pk2(f0, f0), F1 = pk2(f1, f1), F2 = pk2(f2v, f2v),
                       F3 = pk2(f3, f3), F4 = pk2(f4, f4);

    float a0 = 1e38f, a1 = 1e38f, a2 = 1e38f, a3 = 1e38f, a4 = 1e38f;   // fg
    float b0 = 1e38f, b1 = 1e38f, b2 = 1e38f, b3 = 1e38f, b4 = 1e38f;   // bg

    scan_class(&sneg[0],          F0, F1, F2, F3, F4, a0, a1, a2, a3, a4);
    scan_class(&sneg[5 * NPAIR],  F0, F1, F2, F3, F4, b0, b1, b2, b3, b4);

    // fg count in merged top-5: a_i included iff i + #{b_j < a_i} <= 4
    // (strict < encodes fg-wins-ties: all fg train indices precede bg ones)
    int cnt = 0;
    {
        int l0 = (b0 < a0) + (b1 < a0) + (b2 < a0) + (b3 < a0) + (b4 < a0);
        int l1 = (b0 < a1) + (b1 < a1) + (b2 < a1) + (b3 < a1) + (b4 < a1);
        int l2 = (b0 < a2) + (b1 < a2) + (b2 < a2) + (b3 < a2) + (b4 < a2);
        int l3 = (b0 < a3) + (b1 < a3) + (b2 < a3) + (b3 < a3) + (b4 < a3);
        int l4 = (b0 < a4) + (b1 < a4) + (b2 < a4) + (b3 < a4) + (b4 < a4);
        cnt = (0 + l0 <= 4) + (1 + l1 <= 4) + (2 + l2 <= 4) + (3 + l3 <= 4) + (4 + l4 <= 4);
    }
    bool seg = (cnt >= 2);   // probas = cnt/5 >= 0.3

    float* o = out + (size_t)b * NPIX * 3 + (size_t)p * 3;
    o[0] = seg ? v0 : 0.0f;
    o[1] = seg ? v1 : 0.0f;
    o[2] = seg ? v2 : 0.0f;
}

// ---------------------------------------------------------------------------
// host: derive JAX keys — partitionable threefry (default since JAX 0.4.36)
// ---------------------------------------------------------------------------
static void compute_keys(Keys& kp)
{
    for (int b = 0; b < NIMG; ++b) {
        unsigned int ik0, ik1;
        threefry2x32(0u, 42u, 0u, (unsigned int)b, ik0, ik1);   // split(key(42),32)[b]
        unsigned int f0, f1, g0, g1;
        threefry2x32(ik0, ik1, 0u, 0u, f0, f1);                 // split(imgkey)[0] = k_fg
        threefry2x32(ik0, ik1, 0u, 1u, g0, g1);                 // split(imgkey)[1] = k_bg
        kp.k[b][0] = f0; kp.k[b][1] = f1;
        kp.k[b][2] = g0; kp.k[b][3] = g1;
    }
}

extern "C" void kernel_launch(void* const* d_in, const int* in_sizes, int n_in,
                              void* d_out, int out_size)
{
    const float* img = (const float*)d_in[0];
    float* out = (float*)d_out;
    (void)in_sizes; (void)n_in; (void)out_size;

    Keys kp;
    compute_keys(kp);

    dim3 g1(NIMG, 2);
    k1_sample<<<g1, 1024>>>(img, kp);
    k1b_build<<<NIMG, 256>>>(img);
    dim3 g2(NPIX / 256, NIMG);
    k2_knn<<<g2, 256>>>(img, out);
}